// round 1
// baseline (speedup 1.0000x reference)
#include <cuda_runtime.h>
#include <math.h>

#define HID   1152
#define NH    16
#define HD    72
#define TXT   256
#define BATCH 8
#define SEQ   1280
#define TOK   (BATCH*SEQ)   /* 10240 */
#define EPS   1e-6f

// ---------------- scratch (device globals; no allocations allowed) ----------
__device__ float g_mod [BATCH*6*HID];   // adaLN modulation (8 x 6912)
__device__ float g_res [TOK*HID];       // LN-modulated activations
__device__ float g_qkv [TOK*3*HID];     // qkv projections
__device__ float g_attn[TOK*HID];       // attention output (token-major)
__device__ float g_h   [TOK*4*HID];     // mlp hidden

// ---------------- adaLN: mod = silu(c) @ w_ada + b_ada ----------------------
__global__ void k_ada(const float* __restrict__ c,
                      const float* __restrict__ w,
                      const float* __restrict__ bias)
{
    __shared__ float sc[HID];
    int b = blockIdx.y;
    for (int i = threadIdx.x; i < HID; i += blockDim.x) {
        float v = c[b*HID + i];
        sc[i] = v / (1.f + __expf(-v));
    }
    __syncthreads();
    int n = blockIdx.x*128 + threadIdx.x;   // 0..6911
    float acc = bias[n];
    #pragma unroll 4
    for (int k = 0; k < HID; k++) acc += sc[k] * w[(size_t)k*(6*HID) + n];
    g_mod[b*6*HID + n] = acc;
}

// ---------------- fused LayerNorm + modulate: (1+sc)*ln(x)+sh ---------------
__global__ void k_lnmod(const float* __restrict__ x, float* __restrict__ out,
                        int shofs, int scofs)
{
    int row = blockIdx.x;           // token
    int b   = row / SEQ;
    int t   = threadIdx.x;          // 0..287 (288 = 1152/4)
    float4 v = ((const float4*)(x + (size_t)row*HID))[t];
    float s  = v.x + v.y + v.z + v.w;
    float ss = v.x*v.x + v.y*v.y + v.z*v.z + v.w*v.w;
    #pragma unroll
    for (int off = 16; off >= 1; off >>= 1) {
        s  += __shfl_xor_sync(0xffffffffu, s , off);
        ss += __shfl_xor_sync(0xffffffffu, ss, off);
    }
    __shared__ float rs[9], rss[9];
    __shared__ float smu, srs;
    if ((t & 31) == 0) { rs[t>>5] = s; rss[t>>5] = ss; }
    __syncthreads();
    if (t == 0) {
        float S = 0.f, SS = 0.f;
        #pragma unroll
        for (int i = 0; i < 9; i++) { S += rs[i]; SS += rss[i]; }
        float mu  = S * (1.f/(float)HID);
        float var = SS * (1.f/(float)HID) - mu*mu;
        smu = mu; srs = rsqrtf(var + EPS);
    }
    __syncthreads();
    float mu = smu, r = srs;
    float4 sh = ((const float4*)(g_mod + b*6*HID + shofs))[t];
    float4 sc = ((const float4*)(g_mod + b*6*HID + scofs))[t];
    float4 o;
    o.x = (1.f+sc.x)*((v.x-mu)*r) + sh.x;
    o.y = (1.f+sc.y)*((v.y-mu)*r) + sh.y;
    o.z = (1.f+sc.z)*((v.z-mu)*r) + sh.z;
    o.w = (1.f+sc.w)*((v.w-mu)*r) + sh.w;
    ((float4*)(out + (size_t)row*HID))[t] = o;
}

// ---------------- gelu(tanh) -------------------------------------------------
__device__ __forceinline__ float gelu_tanh(float t) {
    return 0.5f*t*(1.f + tanhf(0.7978845608028654f*(t + 0.044715f*t*t*t)));
}

// ---------------- fp32 tiled GEMM: C = epilogue(A@B + bias) ------------------
// A: MxK row-major, B: KxN row-major. M%128==0, N%128==0, K%8==0.
// mode 0: C = acc+bias
// mode 1: C = xres + g_mod[b,gofs+col]*(acc+bias)
// mode 2: C = gelu(acc+bias)
__global__ __launch_bounds__(256,2)
void k_gemm(const float* __restrict__ A, const float* __restrict__ B,
            const float* __restrict__ bias, float* C,
            int M, int N, int K, int mode, const float* xres, int gofs)
{
    __shared__ float As[8][128];
    __shared__ float Bs[8][128];
    int m0 = blockIdx.y*128, n0 = blockIdx.x*128;
    int t  = threadIdx.x;
    int tr = t >> 4, tc = t & 15;
    int ar = t >> 1, ac = (t & 1)*4;
    int br = t >> 5, bc = (t & 31)*4;

    float acc[8][8];
    #pragma unroll
    for (int i = 0; i < 8; i++)
        #pragma unroll
        for (int j = 0; j < 8; j++) acc[i][j] = 0.f;

    const float* Ag = A + (size_t)(m0 + ar)*K + ac;
    const float* Bg = B + (size_t)br*N + n0 + bc;

    for (int k0 = 0; k0 < K; k0 += 8) {
        float4 av = *(const float4*)(Ag + k0);
        float4 bv = *(const float4*)(Bg + (size_t)k0*N);
        __syncthreads();
        As[ac+0][ar] = av.x; As[ac+1][ar] = av.y;
        As[ac+2][ar] = av.z; As[ac+3][ar] = av.w;
        *(float4*)&Bs[br][bc] = bv;
        __syncthreads();
        #pragma unroll
        for (int k = 0; k < 8; k++) {
            float4 a0 = *(const float4*)&As[k][tr*8];
            float4 a1 = *(const float4*)&As[k][tr*8+4];
            float4 b0 = *(const float4*)&Bs[k][tc*8];
            float4 b1 = *(const float4*)&Bs[k][tc*8+4];
            float ax[8] = {a0.x,a0.y,a0.z,a0.w,a1.x,a1.y,a1.z,a1.w};
            float bx[8] = {b0.x,b0.y,b0.z,b0.w,b1.x,b1.y,b1.z,b1.w};
            #pragma unroll
            for (int i = 0; i < 8; i++)
                #pragma unroll
                for (int j = 0; j < 8; j++)
                    acc[i][j] += ax[i]*bx[j];
        }
    }

    #pragma unroll
    for (int i = 0; i < 8; i++) {
        int row = m0 + tr*8 + i;
        int bq  = row / SEQ;
        float*       crow = C + (size_t)row*N + n0 + tc*8;
        const float* xrow = xres ? (xres + (size_t)row*N + n0 + tc*8) : nullptr;
        #pragma unroll
        for (int j = 0; j < 8; j += 4) {
            int col = n0 + tc*8 + j;
            float4 bb = *(const float4*)(bias + col);
            float4 v;
            v.x = acc[i][j+0] + bb.x;
            v.y = acc[i][j+1] + bb.y;
            v.z = acc[i][j+2] + bb.z;
            v.w = acc[i][j+3] + bb.w;
            if (mode == 1) {
                float4 g  = *(const float4*)(g_mod + bq*6*HID + gofs + col);
                float4 xr = *(const float4*)(xrow + j);
                v.x = xr.x + g.x*v.x; v.y = xr.y + g.y*v.y;
                v.z = xr.z + g.z*v.z; v.w = xr.w + g.w*v.w;
            } else if (mode == 2) {
                v.x = gelu_tanh(v.x); v.y = gelu_tanh(v.y);
                v.z = gelu_tanh(v.z); v.w = gelu_tanh(v.w);
            }
            *(float4*)(crow + j) = v;
        }
    }
}

// ---------------- RoPE on q,k for positions >= TXT ---------------------------
__global__ void k_rope(const float* __restrict__ cosb, const float* __restrict__ sinb)
{
    int idx = blockIdx.x*256 + threadIdx.x;      // 8*1024*16*36 threads
    int d = idx % 36;
    int h = (idx / 36) % NH;
    int p = (idx / (36*NH)) % 1024;
    int b = idx / (36*NH*1024);
    int row = b*SEQ + TXT + p;
    size_t base = (size_t)row*(3*HID) + h*HD + d;
    float cv = cosb[p*36 + d], sv = sinb[p*36 + d];
    float q1 = g_qkv[base],        q2 = g_qkv[base+36];
    g_qkv[base]      = q1*cv - q2*sv;
    g_qkv[base+36]   = q1*sv + q2*cv;
    float k1 = g_qkv[base+HID],    k2 = g_qkv[base+HID+36];
    g_qkv[base+HID]    = k1*cv - k2*sv;
    g_qkv[base+HID+36] = k1*sv + k2*cv;
}

// ---------------- flash attention: Q-tile 64, K/V-tile 64 --------------------
#define ROWP 76   // padded head-dim stride in smem (16B aligned, low conflicts)
__global__ __launch_bounds__(256)
void k_attn(const float* __restrict__ qkv, float* __restrict__ out)
{
    extern __shared__ float sm[];
    float* Qs = sm;                 // 64*76
    float* Ks = Qs + 64*ROWP;
    float* Vs = Ks + 64*ROWP;
    float* Os = Vs + 64*ROWP;
    float* Ps = Os + 64*ROWP;       // 64*64
    float* mrow = Ps + 64*64;
    float* lrow = mrow + 64;
    float* crow = lrow + 64;

    int q0 = blockIdx.x*64;
    int h  = blockIdx.y;
    int b  = blockIdx.z;
    int t  = threadIdx.x;
    int ti = t >> 4, tj = t & 15;
    const float scale = 0.11785113019775793f;   // 1/sqrt(72)

    for (int idx = t; idx < 64*72; idx += 256) {
        int i = idx/72, d = idx%72;
        int row = b*SEQ + q0 + i;
        Qs[i*ROWP + d] = qkv[(size_t)row*(3*HID) + h*HD + d];
        Os[i*ROWP + d] = 0.f;
    }
    if (t < 64) { mrow[t] = -3.0e38f; lrow[t] = 0.f; }
    __syncthreads();

    for (int kt = 0; kt < SEQ; kt += 64) {
        for (int idx = t; idx < 64*72; idx += 256) {
            int j = idx/72, d = idx%72;
            int row = b*SEQ + kt + j;
            Ks[j*ROWP + d] = qkv[(size_t)row*(3*HID) +   HID + h*HD + d];
            Vs[j*ROWP + d] = qkv[(size_t)row*(3*HID) + 2*HID + h*HD + d];
        }
        __syncthreads();

        // S = scale * Q K^T  (4x4 per thread)
        float acc[4][4];
        #pragma unroll
        for (int a = 0; a < 4; a++)
            #pragma unroll
            for (int c2 = 0; c2 < 4; c2++) acc[a][c2] = 0.f;
        #pragma unroll
        for (int d = 0; d < 72; d += 4) {
            float4 qa[4], kb[4];
            #pragma unroll
            for (int a = 0; a < 4; a++)  qa[a] = *(const float4*)&Qs[(ti*4+a)*ROWP + d];
            #pragma unroll
            for (int c2 = 0; c2 < 4; c2++) kb[c2] = *(const float4*)&Ks[(tj*4+c2)*ROWP + d];
            #pragma unroll
            for (int a = 0; a < 4; a++)
                #pragma unroll
                for (int c2 = 0; c2 < 4; c2++)
                    acc[a][c2] += qa[a].x*kb[c2].x + qa[a].y*kb[c2].y
                                + qa[a].z*kb[c2].z + qa[a].w*kb[c2].w;
        }

        // online softmax per row group (16 lanes share 4 rows)
        #pragma unroll
        for (int a = 0; a < 4; a++) {
            int row = ti*4 + a;
            float oldm = mrow[row];              // read precedes shfl barrier
            float tm = -3.0e38f;
            #pragma unroll
            for (int c2 = 0; c2 < 4; c2++) {
                acc[a][c2] *= scale;
                tm = fmaxf(tm, acc[a][c2]);
            }
            #pragma unroll
            for (int off = 8; off >= 1; off >>= 1)
                tm = fmaxf(tm, __shfl_xor_sync(0xffffffffu, tm, off));
            float newm = fmaxf(oldm, tm);
            float rsum = 0.f;
            #pragma unroll
            for (int c2 = 0; c2 < 4; c2++) {
                float p = __expf(acc[a][c2] - newm);
                Ps[row*64 + tj*4 + c2] = p;
                rsum += p;
            }
            #pragma unroll
            for (int off = 8; off >= 1; off >>= 1)
                rsum += __shfl_xor_sync(0xffffffffu, rsum, off);
            if (tj == 0) {
                float cf = __expf(oldm - newm);
                crow[row] = cf;
                lrow[row] = lrow[row]*cf + rsum;
                mrow[row] = newm;
            }
        }
        __syncthreads();

        // O = O*c + P V  (float4 over head dim)
        for (int idx = t; idx < 64*18; idx += 256) {
            int i = idx/18, d0 = (idx%18)*4;
            float cf = crow[i];
            float4 o = *(float4*)&Os[i*ROWP + d0];
            o.x *= cf; o.y *= cf; o.z *= cf; o.w *= cf;
            const float* prow = Ps + i*64;
            #pragma unroll 8
            for (int j = 0; j < 64; j++) {
                float p = prow[j];
                float4 v = *(const float4*)&Vs[j*ROWP + d0];
                o.x += p*v.x; o.y += p*v.y; o.z += p*v.z; o.w += p*v.w;
            }
            *(float4*)&Os[i*ROWP + d0] = o;
        }
        __syncthreads();
    }

    for (int idx = t; idx < 64*18; idx += 256) {
        int i = idx/18, d0 = (idx%18)*4;
        float inv = 1.f / lrow[i];
        float4 o = *(float4*)&Os[i*ROWP + d0];
        o.x *= inv; o.y *= inv; o.z *= inv; o.w *= inv;
        int row = b*SEQ + q0 + i;
        *(float4*)(out + (size_t)row*HID + h*HD + d0) = o;
    }
}

// ---------------- launcher ---------------------------------------------------
extern "C" void kernel_launch(void* const* d_in, const int* in_sizes, int n_in,
                              void* d_out, int out_size)
{
    const float* x      = (const float*)d_in[0];
    const float* c      = (const float*)d_in[1];
    const float* cosb   = (const float*)d_in[2];
    const float* sinb   = (const float*)d_in[3];
    const float* w_qkv  = (const float*)d_in[4];
    const float* b_qkv  = (const float*)d_in[5];
    const float* w_proj = (const float*)d_in[6];
    const float* b_proj = (const float*)d_in[7];
    const float* w_mlp1 = (const float*)d_in[8];
    const float* b_mlp1 = (const float*)d_in[9];
    const float* w_mlp2 = (const float*)d_in[10];
    const float* b_mlp2 = (const float*)d_in[11];
    const float* w_ada  = (const float*)d_in[12];
    const float* b_ada  = (const float*)d_in[13];
    float* out = (float*)d_out;

    float *res, *qkv, *attn, *hbuf;
    cudaGetSymbolAddress((void**)&res,  g_res);
    cudaGetSymbolAddress((void**)&qkv,  g_qkv);
    cudaGetSymbolAddress((void**)&attn, g_attn);
    cudaGetSymbolAddress((void**)&hbuf, g_h);

    // 1. adaLN modulation
    k_ada<<<dim3(6*HID/128, BATCH), 128>>>(c, w_ada, b_ada);
    // 2. LN + (sh_msa, sc_msa)
    k_lnmod<<<TOK, 288>>>(x, res, 0, HID);
    // 3. qkv GEMM
    k_gemm<<<dim3(3*HID/128, TOK/128), 256>>>(res, w_qkv, b_qkv, qkv,
                                              TOK, 3*HID, HID, 0, nullptr, 0);
    // 4. RoPE
    k_rope<<<(BATCH*1024*NH*36)/256, 256>>>(cosb, sinb);
    // 5. attention
    int smem = (4*64*ROWP + 64*64 + 3*64) * (int)sizeof(float);
    cudaFuncSetAttribute(k_attn, cudaFuncAttributeMaxDynamicSharedMemorySize, smem);
    k_attn<<<dim3(SEQ/64, NH, BATCH), 256, smem>>>(qkv, attn);
    // 6. proj GEMM + gated residual -> out holds x1
    k_gemm<<<dim3(HID/128, TOK/128), 256>>>(attn, w_proj, b_proj, out,
                                            TOK, HID, HID, 1, x, 2*HID);
    // 7. LN + (sh_mlp, sc_mlp)
    k_lnmod<<<TOK, 288>>>(out, res, 3*HID, 4*HID);
    // 8. mlp1 GEMM + gelu
    k_gemm<<<dim3(4*HID/128, TOK/128), 256>>>(res, w_mlp1, b_mlp1, hbuf,
                                              TOK, 4*HID, HID, 2, nullptr, 0);
    // 9. mlp2 GEMM + gated residual (in-place on out)
    k_gemm<<<dim3(HID/128, TOK/128), 256>>>(hbuf, w_mlp2, b_mlp2, out,
                                            TOK, HID, 4*HID, 1, out, 5*HID);
}

// round 2
// speedup vs baseline: 1.5007x; 1.5007x over previous
#include <cuda_runtime.h>
#include <cuda_bf16.h>
#include <math.h>

#define HID   1152
#define NH    16
#define HD    72
#define TXT   256
#define BATCH 8
#define SEQ   1280
#define TOK   (BATCH*SEQ)   /* 10240 */
#define EPS   1e-6f

// ---------------- scratch (device globals; no allocations allowed) ----------
__device__ float g_mod [BATCH*6*HID];   // adaLN modulation (8 x 6912)
__device__ float g_res [TOK*HID];       // LN-modulated activations
__device__ float g_qkv [TOK*3*HID];     // qkv projections
__device__ float g_attn[TOK*HID];       // attention output (token-major)
__device__ float g_h   [TOK*4*HID];     // mlp hidden

// ---------------- adaLN: mod = silu(c) @ w_ada + b_ada ----------------------
__global__ void k_ada(const float* __restrict__ c,
                      const float* __restrict__ w,
                      const float* __restrict__ bias)
{
    __shared__ float sc[HID];
    int b = blockIdx.y;
    for (int i = threadIdx.x; i < HID; i += blockDim.x) {
        float v = c[b*HID + i];
        sc[i] = v / (1.f + __expf(-v));
    }
    __syncthreads();
    int n = blockIdx.x*128 + threadIdx.x;   // 0..6911
    float acc = bias[n];
    #pragma unroll 4
    for (int k = 0; k < HID; k++) acc += sc[k] * w[(size_t)k*(6*HID) + n];
    g_mod[b*6*HID + n] = acc;
}

// ---------------- fused LayerNorm + modulate: (1+sc)*ln(x)+sh ---------------
__global__ void k_lnmod(const float* __restrict__ x, float* __restrict__ out,
                        int shofs, int scofs)
{
    int row = blockIdx.x;           // token
    int b   = row / SEQ;
    int t   = threadIdx.x;          // 0..287 (288 = 1152/4)
    float4 v = ((const float4*)(x + (size_t)row*HID))[t];
    float s  = v.x + v.y + v.z + v.w;
    float ss = v.x*v.x + v.y*v.y + v.z*v.z + v.w*v.w;
    #pragma unroll
    for (int off = 16; off >= 1; off >>= 1) {
        s  += __shfl_xor_sync(0xffffffffu, s , off);
        ss += __shfl_xor_sync(0xffffffffu, ss, off);
    }
    __shared__ float rs[9], rss[9];
    __shared__ float smu, srs;
    if ((t & 31) == 0) { rs[t>>5] = s; rss[t>>5] = ss; }
    __syncthreads();
    if (t == 0) {
        float S = 0.f, SS = 0.f;
        #pragma unroll
        for (int i = 0; i < 9; i++) { S += rs[i]; SS += rss[i]; }
        float mu  = S * (1.f/(float)HID);
        float var = SS * (1.f/(float)HID) - mu*mu;
        smu = mu; srs = rsqrtf(var + EPS);
    }
    __syncthreads();
    float mu = smu, r = srs;
    float4 sh = ((const float4*)(g_mod + b*6*HID + shofs))[t];
    float4 sc = ((const float4*)(g_mod + b*6*HID + scofs))[t];
    float4 o;
    o.x = (1.f+sc.x)*((v.x-mu)*r) + sh.x;
    o.y = (1.f+sc.y)*((v.y-mu)*r) + sh.y;
    o.z = (1.f+sc.z)*((v.z-mu)*r) + sh.z;
    o.w = (1.f+sc.w)*((v.w-mu)*r) + sh.w;
    ((float4*)(out + (size_t)row*HID))[t] = o;
}

// ---------------- gelu(tanh) -------------------------------------------------
__device__ __forceinline__ float gelu_tanh(float t) {
    return 0.5f*t*(1.f + tanhf(0.7978845608028654f*(t + 0.044715f*t*t*t)));
}

// ---------------- bf16 split helpers ----------------------------------------
__device__ __forceinline__ void split2(float x0, float x1,
                                       unsigned &hi, unsigned &lo)
{
    __nv_bfloat16 h0 = __float2bfloat16_rn(x0);
    __nv_bfloat16 h1 = __float2bfloat16_rn(x1);
    float r0 = x0 - __bfloat162float(h0);
    float r1 = x1 - __bfloat162float(h1);
    __nv_bfloat16 l0 = __float2bfloat16_rn(r0);
    __nv_bfloat16 l1 = __float2bfloat16_rn(r1);
    hi = (unsigned)__bfloat16_as_ushort(h0) | ((unsigned)__bfloat16_as_ushort(h1) << 16);
    lo = (unsigned)__bfloat16_as_ushort(l0) | ((unsigned)__bfloat16_as_ushort(l1) << 16);
}

__device__ __forceinline__ unsigned su32(const void* p) {
    return (unsigned)__cvta_generic_to_shared(p);
}
__device__ __forceinline__ void ldsm4(unsigned &r0, unsigned &r1,
                                      unsigned &r2, unsigned &r3, unsigned a)
{
    asm volatile("ldmatrix.sync.aligned.m8n8.x4.shared.b16 {%0,%1,%2,%3},[%4];\n"
                 : "=r"(r0), "=r"(r1), "=r"(r2), "=r"(r3) : "r"(a));
}
__device__ __forceinline__ void ldsm4t(unsigned &r0, unsigned &r1,
                                       unsigned &r2, unsigned &r3, unsigned a)
{
    asm volatile("ldmatrix.sync.aligned.m8n8.x4.trans.shared.b16 {%0,%1,%2,%3},[%4];\n"
                 : "=r"(r0), "=r"(r1), "=r"(r2), "=r"(r3) : "r"(a));
}
__device__ __forceinline__ void mma16816(float* c, const unsigned* a, const unsigned* b)
{
    asm volatile("mma.sync.aligned.m16n8k16.row.col.f32.bf16.bf16.f32 "
                 "{%0,%1,%2,%3},{%4,%5,%6,%7},{%8,%9},{%0,%1,%2,%3};\n"
                 : "+f"(c[0]), "+f"(c[1]), "+f"(c[2]), "+f"(c[3])
                 : "r"(a[0]), "r"(a[1]), "r"(a[2]), "r"(a[3]),
                   "r"(b[0]), "r"(b[1]));
}

// ---------------- tensor-core GEMM: C = epilogue(A@B + bias) -----------------
// fp32 in/out; internally bf16x3 split (a_hi*b_hi + a_lo*b_hi + a_hi*b_lo).
// A: MxK row-major, B: KxN row-major. M%128==0, N%128==0, K%32==0.
// mode 0: C = acc+bias ; 1: C = xres + g_mod[b,gofs+col]*(acc+bias) ; 2: gelu
#define BK 32
#define APAD 40    /* smem row stride (elems) for A: conflict-free LDSM */
#define BPAD 136   /* smem row stride (elems) for B */
__global__ __launch_bounds__(256)
void k_gemm_tc(const float* __restrict__ A, const float* __restrict__ B,
               const float* __restrict__ bias, float* C,
               int M, int N, int K, int mode, const float* xres, int gofs)
{
    __shared__ __nv_bfloat16 AsH[128][APAD];
    __shared__ __nv_bfloat16 AsL[128][APAD];
    __shared__ __nv_bfloat16 BsH[BK][BPAD];
    __shared__ __nv_bfloat16 BsL[BK][BPAD];

    const int t    = threadIdx.x;
    const int lane = t & 31;
    const int wid  = t >> 5;
    const int m0   = blockIdx.y * 128;
    const int n0   = blockIdx.x * 128;
    const int wm   = (wid >> 2) * 64;      // warp m offset: 0 or 64
    const int wn   = (wid & 3) * 32;       // warp n offset: 0,32,64,96

    // staging indices
    const int ar = t >> 3;                 // 0..31  (A row group)
    const int ac = (t & 7) * 4;            // 0..28  (A k col)
    const int bk = t >> 5;                 // 0..7   (B k row group)
    const int bn = (t & 31) * 4;           // 0..124 (B n col)

    // ldmatrix lane addressing
    const int lrow = lane & 15;
    const int lcol = (lane >> 4) * 8;

    float acc[4][4][4];
    #pragma unroll
    for (int i = 0; i < 4; i++)
        #pragma unroll
        for (int j = 0; j < 4; j++)
            #pragma unroll
            for (int q = 0; q < 4; q++) acc[i][j][q] = 0.f;

    const int nIter = K / BK;
    float4 pa[4], pb[4];

    // prologue: fetch tile 0
    #pragma unroll
    for (int p = 0; p < 4; p++) {
        pa[p] = *(const float4*)(A + (size_t)(m0 + ar + 32*p)*K + ac);
        pb[p] = *(const float4*)(B + (size_t)(bk + 8*p)*N + n0 + bn);
    }

    for (int it = 0; it < nIter; it++) {
        __syncthreads();
        // split + store to smem
        #pragma unroll
        for (int p = 0; p < 4; p++) {
            unsigned h, l;
            int r = ar + 32*p;
            split2(pa[p].x, pa[p].y, h, l);
            *(unsigned*)&AsH[r][ac]   = h;  *(unsigned*)&AsL[r][ac]   = l;
            split2(pa[p].z, pa[p].w, h, l);
            *(unsigned*)&AsH[r][ac+2] = h;  *(unsigned*)&AsL[r][ac+2] = l;
            int kr = bk + 8*p;
            split2(pb[p].x, pb[p].y, h, l);
            *(unsigned*)&BsH[kr][bn]   = h; *(unsigned*)&BsL[kr][bn]   = l;
            split2(pb[p].z, pb[p].w, h, l);
            *(unsigned*)&BsH[kr][bn+2] = h; *(unsigned*)&BsL[kr][bn+2] = l;
        }
        __syncthreads();

        // prefetch next tile (overlaps with mma)
        if (it + 1 < nIter) {
            int k0 = (it + 1) * BK;
            #pragma unroll
            for (int p = 0; p < 4; p++) {
                pa[p] = *(const float4*)(A + (size_t)(m0 + ar + 32*p)*K + k0 + ac);
                pb[p] = *(const float4*)(B + (size_t)(k0 + bk + 8*p)*N + n0 + bn);
            }
        }

        // compute: 2 k-steps of 16
        #pragma unroll
        for (int ks = 0; ks < BK; ks += 16) {
            unsigned aH[4][4], aL[4][4], bH[8], bL[8];
            #pragma unroll
            for (int mt = 0; mt < 4; mt++) {
                unsigned adr = su32(&AsH[wm + mt*16 + lrow][ks + lcol]);
                ldsm4(aH[mt][0], aH[mt][1], aH[mt][2], aH[mt][3], adr);
                adr = su32(&AsL[wm + mt*16 + lrow][ks + lcol]);
                ldsm4(aL[mt][0], aL[mt][1], aL[mt][2], aL[mt][3], adr);
            }
            #pragma unroll
            for (int bt = 0; bt < 2; bt++) {
                unsigned adr = su32(&BsH[ks + lrow][wn + bt*16 + lcol]);
                ldsm4t(bH[bt*4+0], bH[bt*4+1], bH[bt*4+2], bH[bt*4+3], adr);
                adr = su32(&BsL[ks + lrow][wn + bt*16 + lcol]);
                ldsm4t(bL[bt*4+0], bL[bt*4+1], bL[bt*4+2], bL[bt*4+3], adr);
            }
            #pragma unroll
            for (int mt = 0; mt < 4; mt++)
                #pragma unroll
                for (int nt = 0; nt < 4; nt++) {
                    mma16816(acc[mt][nt], aH[mt], &bH[nt*2]);
                    mma16816(acc[mt][nt], aL[mt], &bH[nt*2]);
                    mma16816(acc[mt][nt], aH[mt], &bL[nt*2]);
                }
        }
    }

    // epilogue
    const int gr = lane >> 2;          // 0..7
    const int gc = (lane & 3) * 2;     // 0,2,4,6
    #pragma unroll
    for (int mt = 0; mt < 4; mt++) {
        #pragma unroll
        for (int half = 0; half < 2; half++) {
            int row = m0 + wm + mt*16 + gr + half*8;
            int bq  = row / SEQ;
            #pragma unroll
            for (int nt = 0; nt < 4; nt++) {
                int col = n0 + wn + nt*8 + gc;
                float2 bb = *(const float2*)(bias + col);
                float v0 = acc[mt][nt][half*2+0] + bb.x;
                float v1 = acc[mt][nt][half*2+1] + bb.y;
                if (mode == 1) {
                    float2 g  = *(const float2*)(g_mod + bq*6*HID + gofs + col);
                    float2 xr = *(const float2*)(xres + (size_t)row*N + col);
                    v0 = xr.x + g.x*v0;
                    v1 = xr.y + g.y*v1;
                } else if (mode == 2) {
                    v0 = gelu_tanh(v0);
                    v1 = gelu_tanh(v1);
                }
                float2 o; o.x = v0; o.y = v1;
                *(float2*)(C + (size_t)row*N + col) = o;
            }
        }
    }
}

// ---------------- RoPE on q,k for positions >= TXT ---------------------------
__global__ void k_rope(const float* __restrict__ cosb, const float* __restrict__ sinb)
{
    int idx = blockIdx.x*256 + threadIdx.x;      // 8*1024*16*36 threads
    int d = idx % 36;
    int h = (idx / 36) % NH;
    int p = (idx / (36*NH)) % 1024;
    int b = idx / (36*NH*1024);
    int row = b*SEQ + TXT + p;
    size_t base = (size_t)row*(3*HID) + h*HD + d;
    float cv = cosb[p*36 + d], sv = sinb[p*36 + d];
    float q1 = g_qkv[base],        q2 = g_qkv[base+36];
    g_qkv[base]      = q1*cv - q2*sv;
    g_qkv[base+36]   = q1*sv + q2*cv;
    float k1 = g_qkv[base+HID],    k2 = g_qkv[base+HID+36];
    g_qkv[base+HID]    = k1*cv - k2*sv;
    g_qkv[base+HID+36] = k1*sv + k2*cv;
}

// ---------------- flash attention: Q-tile 64, K/V-tile 64 --------------------
#define ROWP 76   // padded head-dim stride in smem
__global__ __launch_bounds__(256)
void k_attn(const float* __restrict__ qkv, float* __restrict__ out)
{
    extern __shared__ float sm[];
    float* Qs = sm;                 // 64*76
    float* Ks = Qs + 64*ROWP;
    float* Vs = Ks + 64*ROWP;
    float* Os = Vs + 64*ROWP;
    float* Ps = Os + 64*ROWP;       // 64*64
    float* mrow = Ps + 64*64;
    float* lrow = mrow + 64;
    float* crow = lrow + 64;

    int q0 = blockIdx.x*64;
    int h  = blockIdx.y;
    int b  = blockIdx.z;
    int t  = threadIdx.x;
    int ti = t >> 4, tj = t & 15;
    const float scale = 0.11785113019775793f;   // 1/sqrt(72)

    for (int idx = t; idx < 64*72; idx += 256) {
        int i = idx/72, d = idx%72;
        int row = b*SEQ + q0 + i;
        Qs[i*ROWP + d] = qkv[(size_t)row*(3*HID) + h*HD + d];
        Os[i*ROWP + d] = 0.f;
    }
    if (t < 64) { mrow[t] = -3.0e38f; lrow[t] = 0.f; }
    __syncthreads();

    for (int kt = 0; kt < SEQ; kt += 64) {
        for (int idx = t; idx < 64*72; idx += 256) {
            int j = idx/72, d = idx%72;
            int row = b*SEQ + kt + j;
            Ks[j*ROWP + d] = qkv[(size_t)row*(3*HID) +   HID + h*HD + d];
            Vs[j*ROWP + d] = qkv[(size_t)row*(3*HID) + 2*HID + h*HD + d];
        }
        __syncthreads();

        float acc[4][4];
        #pragma unroll
        for (int a = 0; a < 4; a++)
            #pragma unroll
            for (int c2 = 0; c2 < 4; c2++) acc[a][c2] = 0.f;
        #pragma unroll
        for (int d = 0; d < 72; d += 4) {
            float4 qa[4], kb[4];
            #pragma unroll
            for (int a = 0; a < 4; a++)  qa[a] = *(const float4*)&Qs[(ti*4+a)*ROWP + d];
            #pragma unroll
            for (int c2 = 0; c2 < 4; c2++) kb[c2] = *(const float4*)&Ks[(tj*4+c2)*ROWP + d];
            #pragma unroll
            for (int a = 0; a < 4; a++)
                #pragma unroll
                for (int c2 = 0; c2 < 4; c2++)
                    acc[a][c2] += qa[a].x*kb[c2].x + qa[a].y*kb[c2].y
                                + qa[a].z*kb[c2].z + qa[a].w*kb[c2].w;
        }

        #pragma unroll
        for (int a = 0; a < 4; a++) {
            int row = ti*4 + a;
            float oldm = mrow[row];
            float tm = -3.0e38f;
            #pragma unroll
            for (int c2 = 0; c2 < 4; c2++) {
                acc[a][c2] *= scale;
                tm = fmaxf(tm, acc[a][c2]);
            }
            #pragma unroll
            for (int off = 8; off >= 1; off >>= 1)
                tm = fmaxf(tm, __shfl_xor_sync(0xffffffffu, tm, off));
            float newm = fmaxf(oldm, tm);
            float rsum = 0.f;
            #pragma unroll
            for (int c2 = 0; c2 < 4; c2++) {
                float p = __expf(acc[a][c2] - newm);
                Ps[row*64 + tj*4 + c2] = p;
                rsum += p;
            }
            #pragma unroll
            for (int off = 8; off >= 1; off >>= 1)
                rsum += __shfl_xor_sync(0xffffffffu, rsum, off);
            if (tj == 0) {
                float cf = __expf(oldm - newm);
                crow[row] = cf;
                lrow[row] = lrow[row]*cf + rsum;
                mrow[row] = newm;
            }
        }
        __syncthreads();

        for (int idx = t; idx < 64*18; idx += 256) {
            int i = idx/18, d0 = (idx%18)*4;
            float cf = crow[i];
            float4 o = *(float4*)&Os[i*ROWP + d0];
            o.x *= cf; o.y *= cf; o.z *= cf; o.w *= cf;
            const float* prow = Ps + i*64;
            #pragma unroll 8
            for (int j = 0; j < 64; j++) {
                float p = prow[j];
                float4 v = *(const float4*)&Vs[j*ROWP + d0];
                o.x += p*v.x; o.y += p*v.y; o.z += p*v.z; o.w += p*v.w;
            }
            *(float4*)&Os[i*ROWP + d0] = o;
        }
        __syncthreads();
    }

    for (int idx = t; idx < 64*18; idx += 256) {
        int i = idx/18, d0 = (idx%18)*4;
        float inv = 1.f / lrow[i];
        float4 o = *(float4*)&Os[i*ROWP + d0];
        o.x *= inv; o.y *= inv; o.z *= inv; o.w *= inv;
        int row = b*SEQ + q0 + i;
        *(float4*)(out + (size_t)row*HID + h*HD + d0) = o;
    }
}

// ---------------- launcher ---------------------------------------------------
extern "C" void kernel_launch(void* const* d_in, const int* in_sizes, int n_in,
                              void* d_out, int out_size)
{
    const float* x      = (const float*)d_in[0];
    const float* c      = (const float*)d_in[1];
    const float* cosb   = (const float*)d_in[2];
    const float* sinb   = (const float*)d_in[3];
    const float* w_qkv  = (const float*)d_in[4];
    const float* b_qkv  = (const float*)d_in[5];
    const float* w_proj = (const float*)d_in[6];
    const float* b_proj = (const float*)d_in[7];
    const float* w_mlp1 = (const float*)d_in[8];
    const float* b_mlp1 = (const float*)d_in[9];
    const float* w_mlp2 = (const float*)d_in[10];
    const float* b_mlp2 = (const float*)d_in[11];
    const float* w_ada  = (const float*)d_in[12];
    const float* b_ada  = (const float*)d_in[13];
    float* out = (float*)d_out;

    float *res, *qkv, *attn, *hbuf;
    cudaGetSymbolAddress((void**)&res,  g_res);
    cudaGetSymbolAddress((void**)&qkv,  g_qkv);
    cudaGetSymbolAddress((void**)&attn, g_attn);
    cudaGetSymbolAddress((void**)&hbuf, g_h);

    // 1. adaLN modulation
    k_ada<<<dim3(6*HID/128, BATCH), 128>>>(c, w_ada, b_ada);
    // 2. LN + (sh_msa, sc_msa)
    k_lnmod<<<TOK, 288>>>(x, res, 0, HID);
    // 3. qkv GEMM (tensor cores, bf16x3)
    k_gemm_tc<<<dim3(3*HID/128, TOK/128), 256>>>(res, w_qkv, b_qkv, qkv,
                                                 TOK, 3*HID, HID, 0, nullptr, 0);
    // 4. RoPE
    k_rope<<<(BATCH*1024*NH*36)/256, 256>>>(cosb, sinb);
    // 5. attention
    int smem = (4*64*ROWP + 64*64 + 3*64) * (int)sizeof(float);
    cudaFuncSetAttribute(k_attn, cudaFuncAttributeMaxDynamicSharedMemorySize, smem);
    k_attn<<<dim3(SEQ/64, NH, BATCH), 256, smem>>>(qkv, attn);
    // 6. proj GEMM + gated residual -> out holds x1
    k_gemm_tc<<<dim3(HID/128, TOK/128), 256>>>(attn, w_proj, b_proj, out,
                                               TOK, HID, HID, 1, x, 2*HID);
    // 7. LN + (sh_mlp, sc_mlp)
    k_lnmod<<<TOK, 288>>>(out, res, 3*HID, 4*HID);
    // 8. mlp1 GEMM + gelu
    k_gemm_tc<<<dim3(4*HID/128, TOK/128), 256>>>(res, w_mlp1, b_mlp1, hbuf,
                                                 TOK, 4*HID, HID, 2, nullptr, 0);
    // 9. mlp2 GEMM + gated residual (in-place on out)
    k_gemm_tc<<<dim3(HID/128, TOK/128), 256>>>(hbuf, w_mlp2, b_mlp2, out,
                                               TOK, HID, 4*HID, 1, out, 5*HID);
}

// round 3
// speedup vs baseline: 1.7574x; 1.1711x over previous
#include <cuda_runtime.h>
#include <cuda_bf16.h>
#include <math.h>

#define HID   1152
#define NH    16
#define HD    72
#define TXT   256
#define BATCH 8
#define SEQ   1280
#define TOK   (BATCH*SEQ)   /* 10240 */
#define EPS   1e-6f

typedef __nv_bfloat16 bf16;

// ---------------- scratch (device globals; no allocations allowed) ----------
__device__ float g_mod [BATCH*6*HID];
__device__ float g_qkv [TOK*3*HID];
__device__ bf16  g_resh[TOK*HID],   g_resl[TOK*HID];
__device__ bf16  g_attnh[TOK*HID],  g_attnl[TOK*HID];
__device__ bf16  g_hh[TOK*4*HID],   g_hl[TOK*4*HID];
__device__ bf16  g_wqkvh[HID*3*HID], g_wqkvl[HID*3*HID];
__device__ bf16  g_wprojh[HID*HID],  g_wprojl[HID*HID];
__device__ bf16  g_wm1h[HID*4*HID],  g_wm1l[HID*4*HID];
__device__ bf16  g_wm2h[4*HID*HID],  g_wm2l[4*HID*HID];

// ---------------- helpers ----------------------------------------------------
__device__ __forceinline__ void split1(float x, bf16 &h, bf16 &l) {
    h = __float2bfloat16_rn(x);
    l = __float2bfloat16_rn(x - __bfloat162float(h));
}
__device__ __forceinline__ unsigned su32(const void* p) {
    return (unsigned)__cvta_generic_to_shared(p);
}
__device__ __forceinline__ void cp16(unsigned dst, const void* src) {
    asm volatile("cp.async.ca.shared.global [%0],[%1],16;\n" :: "r"(dst), "l"(src));
}
__device__ __forceinline__ void cpcommit() {
    asm volatile("cp.async.commit_group;\n");
}
__device__ __forceinline__ void cpwait0() {
    asm volatile("cp.async.wait_group 0;\n");
}
__device__ __forceinline__ void ldsm4(unsigned &r0, unsigned &r1,
                                      unsigned &r2, unsigned &r3, unsigned a)
{
    asm volatile("ldmatrix.sync.aligned.m8n8.x4.shared.b16 {%0,%1,%2,%3},[%4];\n"
                 : "=r"(r0), "=r"(r1), "=r"(r2), "=r"(r3) : "r"(a));
}
__device__ __forceinline__ void ldsm4t(unsigned &r0, unsigned &r1,
                                       unsigned &r2, unsigned &r3, unsigned a)
{
    asm volatile("ldmatrix.sync.aligned.m8n8.x4.trans.shared.b16 {%0,%1,%2,%3},[%4];\n"
                 : "=r"(r0), "=r"(r1), "=r"(r2), "=r"(r3) : "r"(a));
}
__device__ __forceinline__ void mma16816(float* c, const unsigned* a, const unsigned* b)
{
    asm volatile("mma.sync.aligned.m16n8k16.row.col.f32.bf16.bf16.f32 "
                 "{%0,%1,%2,%3},{%4,%5,%6,%7},{%8,%9},{%0,%1,%2,%3};\n"
                 : "+f"(c[0]), "+f"(c[1]), "+f"(c[2]), "+f"(c[3])
                 : "r"(a[0]), "r"(a[1]), "r"(a[2]), "r"(a[3]),
                   "r"(b[0]), "r"(b[1]));
}
__device__ __forceinline__ float gelu_tanh(float t) {
    return 0.5f*t*(1.f + tanhf(0.7978845608028654f*(t + 0.044715f*t*t*t)));
}

// ---------------- weight split: fp32 -> bf16 hi/lo ---------------------------
__global__ void k_split(const float* __restrict__ src, bf16* __restrict__ h,
                        bf16* __restrict__ l, int n4)
{
    int i = blockIdx.x*256 + threadIdx.x;
    if (i >= n4) return;
    float4 v = ((const float4*)src)[i];
    bf16 hh[4], ll[4];
    split1(v.x, hh[0], ll[0]); split1(v.y, hh[1], ll[1]);
    split1(v.z, hh[2], ll[2]); split1(v.w, hh[3], ll[3]);
    ((uint2*)h)[i] = *(uint2*)hh;
    ((uint2*)l)[i] = *(uint2*)ll;
}

// ---------------- adaLN: mod = silu(c) @ w_ada + b_ada ----------------------
__global__ void k_ada(const float* __restrict__ c,
                      const float* __restrict__ w,
                      const float* __restrict__ bias)
{
    __shared__ float sc[HID];
    int b = blockIdx.y;
    for (int i = threadIdx.x; i < HID; i += blockDim.x) {
        float v = c[b*HID + i];
        sc[i] = v / (1.f + __expf(-v));
    }
    __syncthreads();
    int n = blockIdx.x*128 + threadIdx.x;
    float acc = bias[n];
    #pragma unroll 4
    for (int k = 0; k < HID; k++) acc += sc[k] * w[(size_t)k*(6*HID) + n];
    g_mod[b*6*HID + n] = acc;
}

// ---------------- fused LN + modulate, writes split bf16 ---------------------
__global__ void k_lnmod(const float* __restrict__ x,
                        bf16* __restrict__ oh, bf16* __restrict__ ol,
                        int shofs, int scofs)
{
    int row = blockIdx.x;
    int b   = row / SEQ;
    int t   = threadIdx.x;          // 0..287
    float4 v = ((const float4*)(x + (size_t)row*HID))[t];
    float s  = v.x + v.y + v.z + v.w;
    float ss = v.x*v.x + v.y*v.y + v.z*v.z + v.w*v.w;
    #pragma unroll
    for (int off = 16; off >= 1; off >>= 1) {
        s  += __shfl_xor_sync(0xffffffffu, s , off);
        ss += __shfl_xor_sync(0xffffffffu, ss, off);
    }
    __shared__ float rs[9], rss[9];
    __shared__ float smu, srs;
    if ((t & 31) == 0) { rs[t>>5] = s; rss[t>>5] = ss; }
    __syncthreads();
    if (t == 0) {
        float S = 0.f, SS = 0.f;
        #pragma unroll
        for (int i = 0; i < 9; i++) { S += rs[i]; SS += rss[i]; }
        float mu  = S * (1.f/(float)HID);
        float var = SS * (1.f/(float)HID) - mu*mu;
        smu = mu; srs = rsqrtf(var + EPS);
    }
    __syncthreads();
    float mu = smu, r = srs;
    float4 sh = ((const float4*)(g_mod + b*6*HID + shofs))[t];
    float4 sc = ((const float4*)(g_mod + b*6*HID + scofs))[t];
    float o0 = (1.f+sc.x)*((v.x-mu)*r) + sh.x;
    float o1 = (1.f+sc.y)*((v.y-mu)*r) + sh.y;
    float o2 = (1.f+sc.z)*((v.z-mu)*r) + sh.z;
    float o3 = (1.f+sc.w)*((v.w-mu)*r) + sh.w;
    bf16 hh[4], ll[4];
    split1(o0, hh[0], ll[0]); split1(o1, hh[1], ll[1]);
    split1(o2, hh[2], ll[2]); split1(o3, hh[3], ll[3]);
    ((uint2*)(oh + (size_t)row*HID))[t] = *(uint2*)hh;
    ((uint2*)(ol + (size_t)row*HID))[t] = *(uint2*)ll;
}

// ---------------- tensor-core GEMM over pre-split bf16 operands --------------
// C = epilogue(Ah@Bh + Al@Bh + Ah@Bl + bias)
// A: MxK row-major (hi/lo), B: KxN row-major (hi/lo).
// mode 0: fp32 C = acc+bias
// mode 1: fp32 C = xres + g_mod[b,gofs+col]*(acc+bias)
// mode 2: bf16 split (Ch,Cl) = gelu(acc+bias)
#define BK 32
#define APAD 40
#define BPAD 136
#define SM_A (128*APAD)          /* per-stage A elems */
#define SM_B (BK*BPAD)           /* per-stage B elems */
__global__ __launch_bounds__(256)
void k_gemm_tc(const bf16* __restrict__ Ah, const bf16* __restrict__ Al,
               const bf16* __restrict__ Bh, const bf16* __restrict__ Bl,
               const float* __restrict__ bias,
               float* C, bf16* Ch, bf16* Cl,
               int M, int N, int K, int mode, const float* xres, int gofs)
{
    extern __shared__ bf16 smem[];
    bf16* sAH = smem;                    // [2][128][APAD]
    bf16* sAL = sAH + 2*SM_A;
    bf16* sBH = sAL + 2*SM_A;            // [2][BK][BPAD]
    bf16* sBL = sBH + 2*SM_B;

    const int t    = threadIdx.x;
    const int lane = t & 31;
    const int wid  = t >> 5;
    const int m0   = blockIdx.y * 128;
    const int n0   = blockIdx.x * 128;
    const int wm   = (wid >> 2) * 64;
    const int wn   = (wid & 3) * 32;

    // cp.async staging indices (16B = 8 bf16 per op)
    const int arow = t >> 2;             // 0..63
    const int acol = (t & 3) * 8;        // 0,8,16,24
    const int brow = t >> 4;             // 0..15
    const int bcol = (t & 15) * 8;       // 0..120

    // ldmatrix lane addressing
    const int lrow = lane & 15;
    const int lcol = (lane >> 4) * 8;

    float acc[4][4][4];
    #pragma unroll
    for (int i = 0; i < 4; i++)
        #pragma unroll
        for (int j = 0; j < 4; j++)
            #pragma unroll
            for (int q = 0; q < 4; q++) acc[i][j][q] = 0.f;

    const int nIter = K / BK;

    // issue stage s loads for k-tile it
    auto issue = [&](int it, int s) {
        int k0 = it * BK;
        bf16* aH = sAH + s*SM_A;  bf16* aL = sAL + s*SM_A;
        bf16* bH = sBH + s*SM_B;  bf16* bL = sBL + s*SM_B;
        #pragma unroll
        for (int p = 0; p < 2; p++) {
            int r = arow + 64*p;
            size_t go = (size_t)(m0 + r)*K + k0 + acol;
            cp16(su32(aH + r*APAD + acol), Ah + go);
            cp16(su32(aL + r*APAD + acol), Al + go);
        }
        #pragma unroll
        for (int p = 0; p < 2; p++) {
            int r = brow + 16*p;
            size_t go = (size_t)(k0 + r)*N + n0 + bcol;
            cp16(su32(bH + r*BPAD + bcol), Bh + go);
            cp16(su32(bL + r*BPAD + bcol), Bl + go);
        }
        cpcommit();
    };

    issue(0, 0);

    for (int it = 0; it < nIter; it++) {
        cpwait0();
        __syncthreads();
        if (it + 1 < nIter) issue(it + 1, (it + 1) & 1);

        int s = it & 1;
        bf16* aHs = sAH + s*SM_A;  bf16* aLs = sAL + s*SM_A;
        bf16* bHs = sBH + s*SM_B;  bf16* bLs = sBL + s*SM_B;

        #pragma unroll
        for (int ks = 0; ks < BK; ks += 16) {
            unsigned aH[4][4], aL[4][4], bH[8], bL[8];
            #pragma unroll
            for (int mt = 0; mt < 4; mt++) {
                unsigned adr = su32(aHs + (wm + mt*16 + lrow)*APAD + ks + lcol);
                ldsm4(aH[mt][0], aH[mt][1], aH[mt][2], aH[mt][3], adr);
                adr = su32(aLs + (wm + mt*16 + lrow)*APAD + ks + lcol);
                ldsm4(aL[mt][0], aL[mt][1], aL[mt][2], aL[mt][3], adr);
            }
            #pragma unroll
            for (int bt = 0; bt < 2; bt++) {
                unsigned adr = su32(bHs + (ks + lrow)*BPAD + wn + bt*16 + lcol);
                ldsm4t(bH[bt*4+0], bH[bt*4+1], bH[bt*4+2], bH[bt*4+3], adr);
                adr = su32(bLs + (ks + lrow)*BPAD + wn + bt*16 + lcol);
                ldsm4t(bL[bt*4+0], bL[bt*4+1], bL[bt*4+2], bL[bt*4+3], adr);
            }
            #pragma unroll
            for (int mt = 0; mt < 4; mt++)
                #pragma unroll
                for (int nt = 0; nt < 4; nt++) {
                    mma16816(acc[mt][nt], aH[mt], &bH[nt*2]);
                    mma16816(acc[mt][nt], aL[mt], &bH[nt*2]);
                    mma16816(acc[mt][nt], aH[mt], &bL[nt*2]);
                }
        }
        __syncthreads();
    }

    // epilogue
    const int gr = lane >> 2;
    const int gc = (lane & 3) * 2;
    #pragma unroll
    for (int mt = 0; mt < 4; mt++) {
        #pragma unroll
        for (int half = 0; half < 2; half++) {
            int row = m0 + wm + mt*16 + gr + half*8;
            int bq  = row / SEQ;
            #pragma unroll
            for (int nt = 0; nt < 4; nt++) {
                int col = n0 + wn + nt*8 + gc;
                float2 bb = *(const float2*)(bias + col);
                float v0 = acc[mt][nt][half*2+0] + bb.x;
                float v1 = acc[mt][nt][half*2+1] + bb.y;
                if (mode == 1) {
                    float2 g  = *(const float2*)(g_mod + bq*6*HID + gofs + col);
                    float2 xr = *(const float2*)(xres + (size_t)row*N + col);
                    v0 = xr.x + g.x*v0;
                    v1 = xr.y + g.y*v1;
                    float2 o; o.x = v0; o.y = v1;
                    *(float2*)(C + (size_t)row*N + col) = o;
                } else if (mode == 2) {
                    v0 = gelu_tanh(v0);
                    v1 = gelu_tanh(v1);
                    bf16 h0, l0, h1, l1;
                    split1(v0, h0, l0); split1(v1, h1, l1);
                    bf16 hp[2] = {h0, h1}, lp[2] = {l0, l1};
                    *(unsigned*)(Ch + (size_t)row*N + col) = *(unsigned*)hp;
                    *(unsigned*)(Cl + (size_t)row*N + col) = *(unsigned*)lp;
                } else {
                    float2 o; o.x = v0; o.y = v1;
                    *(float2*)(C + (size_t)row*N + col) = o;
                }
            }
        }
    }
}

// ---------------- RoPE on q,k for positions >= TXT ---------------------------
__global__ void k_rope(const float* __restrict__ cosb, const float* __restrict__ sinb)
{
    int idx = blockIdx.x*256 + threadIdx.x;
    int d = idx % 36;
    int h = (idx / 36) % NH;
    int p = (idx / (36*NH)) % 1024;
    int b = idx / (36*NH*1024);
    int row = b*SEQ + TXT + p;
    size_t base = (size_t)row*(3*HID) + h*HD + d;
    float cv = cosb[p*36 + d], sv = sinb[p*36 + d];
    float q1 = g_qkv[base],        q2 = g_qkv[base+36];
    g_qkv[base]      = q1*cv - q2*sv;
    g_qkv[base+36]   = q1*sv + q2*cv;
    float k1 = g_qkv[base+HID],    k2 = g_qkv[base+HID+36];
    g_qkv[base+HID]    = k1*cv - k2*sv;
    g_qkv[base+HID+36] = k1*sv + k2*cv;
}

// ---------------- flash attention (fp32), epilogue writes split bf16 ---------
#define ROWP 76
__global__ __launch_bounds__(256)
void k_attn(const float* __restrict__ qkv,
            bf16* __restrict__ oh, bf16* __restrict__ ol)
{
    extern __shared__ float sm[];
    float* Qs = sm;
    float* Ks = Qs + 64*ROWP;
    float* Vs = Ks + 64*ROWP;
    float* Os = Vs + 64*ROWP;
    float* Ps = Os + 64*ROWP;
    float* mrow = Ps + 64*64;
    float* lrow = mrow + 64;
    float* crow = lrow + 64;

    int q0 = blockIdx.x*64;
    int h  = blockIdx.y;
    int b  = blockIdx.z;
    int t  = threadIdx.x;
    int ti = t >> 4, tj = t & 15;
    const float scale = 0.11785113019775793f;

    for (int idx = t; idx < 64*72; idx += 256) {
        int i = idx/72, d = idx%72;
        int row = b*SEQ + q0 + i;
        Qs[i*ROWP + d] = qkv[(size_t)row*(3*HID) + h*HD + d];
        Os[i*ROWP + d] = 0.f;
    }
    if (t < 64) { mrow[t] = -3.0e38f; lrow[t] = 0.f; }
    __syncthreads();

    for (int kt = 0; kt < SEQ; kt += 64) {
        for (int idx = t; idx < 64*72; idx += 256) {
            int j = idx/72, d = idx%72;
            int row = b*SEQ + kt + j;
            Ks[j*ROWP + d] = qkv[(size_t)row*(3*HID) +   HID + h*HD + d];
            Vs[j*ROWP + d] = qkv[(size_t)row*(3*HID) + 2*HID + h*HD + d];
        }
        __syncthreads();

        float acc[4][4];
        #pragma unroll
        for (int a = 0; a < 4; a++)
            #pragma unroll
            for (int c2 = 0; c2 < 4; c2++) acc[a][c2] = 0.f;
        #pragma unroll
        for (int d = 0; d < 72; d += 4) {
            float4 qa[4], kb[4];
            #pragma unroll
            for (int a = 0; a < 4; a++)  qa[a] = *(const float4*)&Qs[(ti*4+a)*ROWP + d];
            #pragma unroll
            for (int c2 = 0; c2 < 4; c2++) kb[c2] = *(const float4*)&Ks[(tj*4+c2)*ROWP + d];
            #pragma unroll
            for (int a = 0; a < 4; a++)
                #pragma unroll
                for (int c2 = 0; c2 < 4; c2++)
                    acc[a][c2] += qa[a].x*kb[c2].x + qa[a].y*kb[c2].y
                                + qa[a].z*kb[c2].z + qa[a].w*kb[c2].w;
        }

        #pragma unroll
        for (int a = 0; a < 4; a++) {
            int row = ti*4 + a;
            float oldm = mrow[row];
            float tm = -3.0e38f;
            #pragma unroll
            for (int c2 = 0; c2 < 4; c2++) {
                acc[a][c2] *= scale;
                tm = fmaxf(tm, acc[a][c2]);
            }
            #pragma unroll
            for (int off = 8; off >= 1; off >>= 1)
                tm = fmaxf(tm, __shfl_xor_sync(0xffffffffu, tm, off));
            float newm = fmaxf(oldm, tm);
            float rsum = 0.f;
            #pragma unroll
            for (int c2 = 0; c2 < 4; c2++) {
                float p = __expf(acc[a][c2] - newm);
                Ps[row*64 + tj*4 + c2] = p;
                rsum += p;
            }
            #pragma unroll
            for (int off = 8; off >= 1; off >>= 1)
                rsum += __shfl_xor_sync(0xffffffffu, rsum, off);
            if (tj == 0) {
                float cf = __expf(oldm - newm);
                crow[row] = cf;
                lrow[row] = lrow[row]*cf + rsum;
                mrow[row] = newm;
            }
        }
        __syncthreads();

        for (int idx = t; idx < 64*18; idx += 256) {
            int i = idx/18, d0 = (idx%18)*4;
            float cf = crow[i];
            float4 o = *(float4*)&Os[i*ROWP + d0];
            o.x *= cf; o.y *= cf; o.z *= cf; o.w *= cf;
            const float* prow = Ps + i*64;
            #pragma unroll 8
            for (int j = 0; j < 64; j++) {
                float p = prow[j];
                float4 v = *(const float4*)&Vs[j*ROWP + d0];
                o.x += p*v.x; o.y += p*v.y; o.z += p*v.z; o.w += p*v.w;
            }
            *(float4*)&Os[i*ROWP + d0] = o;
        }
        __syncthreads();
    }

    for (int idx = t; idx < 64*18; idx += 256) {
        int i = idx/18, d0 = (idx%18)*4;
        float inv = 1.f / lrow[i];
        float4 o = *(float4*)&Os[i*ROWP + d0];
        o.x *= inv; o.y *= inv; o.z *= inv; o.w *= inv;
        int row = b*SEQ + q0 + i;
        bf16 hh[4], ll[4];
        split1(o.x, hh[0], ll[0]); split1(o.y, hh[1], ll[1]);
        split1(o.z, hh[2], ll[2]); split1(o.w, hh[3], ll[3]);
        size_t off = (size_t)row*HID + h*HD + d0;
        *(uint2*)(oh + off) = *(uint2*)hh;
        *(uint2*)(ol + off) = *(uint2*)ll;
    }
}

// ---------------- launcher ---------------------------------------------------
extern "C" void kernel_launch(void* const* d_in, const int* in_sizes, int n_in,
                              void* d_out, int out_size)
{
    const float* x      = (const float*)d_in[0];
    const float* c      = (const float*)d_in[1];
    const float* cosb   = (const float*)d_in[2];
    const float* sinb   = (const float*)d_in[3];
    const float* w_qkv  = (const float*)d_in[4];
    const float* b_qkv  = (const float*)d_in[5];
    const float* w_proj = (const float*)d_in[6];
    const float* b_proj = (const float*)d_in[7];
    const float* w_mlp1 = (const float*)d_in[8];
    const float* b_mlp1 = (const float*)d_in[9];
    const float* w_mlp2 = (const float*)d_in[10];
    const float* b_mlp2 = (const float*)d_in[11];
    const float* w_ada  = (const float*)d_in[12];
    const float* b_ada  = (const float*)d_in[13];
    float* out = (float*)d_out;

    float *qkv;
    bf16 *resh, *resl, *attnh, *attnl, *hh, *hl;
    bf16 *wqkvh, *wqkvl, *wprojh, *wprojl, *wm1h, *wm1l, *wm2h, *wm2l;
    cudaGetSymbolAddress((void**)&qkv,   g_qkv);
    cudaGetSymbolAddress((void**)&resh,  g_resh);
    cudaGetSymbolAddress((void**)&resl,  g_resl);
    cudaGetSymbolAddress((void**)&attnh, g_attnh);
    cudaGetSymbolAddress((void**)&attnl, g_attnl);
    cudaGetSymbolAddress((void**)&hh,    g_hh);
    cudaGetSymbolAddress((void**)&hl,    g_hl);
    cudaGetSymbolAddress((void**)&wqkvh, g_wqkvh);
    cudaGetSymbolAddress((void**)&wqkvl, g_wqkvl);
    cudaGetSymbolAddress((void**)&wprojh,g_wprojh);
    cudaGetSymbolAddress((void**)&wprojl,g_wprojl);
    cudaGetSymbolAddress((void**)&wm1h,  g_wm1h);
    cudaGetSymbolAddress((void**)&wm1l,  g_wm1l);
    cudaGetSymbolAddress((void**)&wm2h,  g_wm2h);
    cudaGetSymbolAddress((void**)&wm2l,  g_wm2l);

    // 0. split weights to bf16 hi/lo
    k_split<<<(HID*3*HID/4 + 255)/256, 256>>>(w_qkv,  wqkvh, wqkvl, HID*3*HID/4);
    k_split<<<(HID*HID/4   + 255)/256, 256>>>(w_proj, wprojh, wprojl, HID*HID/4);
    k_split<<<(HID*4*HID/4 + 255)/256, 256>>>(w_mlp1, wm1h, wm1l, HID*4*HID/4);
    k_split<<<(4*HID*HID/4 + 255)/256, 256>>>(w_mlp2, wm2h, wm2l, 4*HID*HID/4);

    // 1. adaLN modulation
    k_ada<<<dim3(6*HID/128, BATCH), 128>>>(c, w_ada, b_ada);
    // 2. LN + (sh_msa, sc_msa) -> split res
    k_lnmod<<<TOK, 288>>>(x, resh, resl, 0, HID);

    int gsmem = (2*SM_A + 2*SM_B) * 2 * (int)sizeof(bf16);
    cudaFuncSetAttribute(k_gemm_tc, cudaFuncAttributeMaxDynamicSharedMemorySize, gsmem);

    // 3. qkv GEMM
    k_gemm_tc<<<dim3(3*HID/128, TOK/128), 256, gsmem>>>(
        resh, resl, wqkvh, wqkvl, b_qkv, qkv, nullptr, nullptr,
        TOK, 3*HID, HID, 0, nullptr, 0);
    // 4. RoPE
    k_rope<<<(BATCH*1024*NH*36)/256, 256>>>(cosb, sinb);
    // 5. attention -> split attn
    int asmem = (4*64*ROWP + 64*64 + 3*64) * (int)sizeof(float);
    cudaFuncSetAttribute(k_attn, cudaFuncAttributeMaxDynamicSharedMemorySize, asmem);
    k_attn<<<dim3(SEQ/64, NH, BATCH), 256, asmem>>>(qkv, attnh, attnl);
    // 6. proj GEMM + gated residual -> out = x1
    k_gemm_tc<<<dim3(HID/128, TOK/128), 256, gsmem>>>(
        attnh, attnl, wprojh, wprojl, b_proj, out, nullptr, nullptr,
        TOK, HID, HID, 1, x, 2*HID);
    // 7. LN + (sh_mlp, sc_mlp) -> split res
    k_lnmod<<<TOK, 288>>>(out, resh, resl, 3*HID, 4*HID);
    // 8. mlp1 GEMM + gelu -> split h
    k_gemm_tc<<<dim3(4*HID/128, TOK/128), 256, gsmem>>>(
        resh, resl, wm1h, wm1l, b_mlp1, nullptr, hh, hl,
        TOK, 4*HID, HID, 2, nullptr, 0);
    // 9. mlp2 GEMM + gated residual (in-place on out)
    k_gemm_tc<<<dim3(HID/128, TOK/128), 256, gsmem>>>(
        hh, hl, wm2h, wm2l, b_mlp2, out, nullptr, nullptr,
        TOK, HID, 4*HID, 1, out, 5*HID);
}

// round 6
// speedup vs baseline: 3.9513x; 2.2483x over previous
#include <cuda_runtime.h>
#include <cuda_bf16.h>
#include <math.h>
#include <stdint.h>

#define HID   1152
#define NH    16
#define HD    72
#define TXT   256
#define BATCH 8
#define SEQ   1280
#define TOK   (BATCH*SEQ)   /* 10240 */
#define EPS   1e-6f

typedef __nv_bfloat16 bf16;

extern __shared__ char dynsmem[];

// ---------------- scratch (device globals; no allocations allowed) ----------
__device__ float g_mod [BATCH*6*HID];
__device__ float g_qkv [TOK*3*HID];
__device__ bf16  g_qkvh[TOK*3*HID], g_qkvl[TOK*3*HID];
__device__ bf16  g_resh[TOK*HID],   g_resl[TOK*HID];
__device__ bf16  g_attnh[TOK*HID],  g_attnl[TOK*HID];
__device__ bf16  g_hh[TOK*4*HID],   g_hl[TOK*4*HID];
__device__ bf16  g_wqkvh[HID*3*HID], g_wqkvl[HID*3*HID];
__device__ bf16  g_wprojh[HID*HID],  g_wprojl[HID*HID];
__device__ bf16  g_wm1h[HID*4*HID],  g_wm1l[HID*4*HID];
__device__ bf16  g_wm2h[4*HID*HID],  g_wm2l[4*HID*HID];

// ---------------- helpers ----------------------------------------------------
__device__ __forceinline__ void split1(float x, bf16 &h, bf16 &l) {
    h = __float2bfloat16_rn(x);
    l = __float2bfloat16_rn(x - __bfloat162float(h));
}
__device__ __forceinline__ unsigned packh2(float a, float b) {
    __nv_bfloat16 ha = __float2bfloat16_rn(a), hb = __float2bfloat16_rn(b);
    return (unsigned)__bfloat16_as_ushort(ha) |
           ((unsigned)__bfloat16_as_ushort(hb) << 16);
}
__device__ __forceinline__ unsigned packl2(float a, float b) {
    float ra = a - __bfloat162float(__float2bfloat16_rn(a));
    float rb = b - __bfloat162float(__float2bfloat16_rn(b));
    return packh2(ra, rb);
}
__device__ __forceinline__ unsigned su32(const void* p) {
    return (unsigned)__cvta_generic_to_shared(p);
}
__device__ __forceinline__ void cp16(unsigned dst, const void* src) {
    asm volatile("cp.async.ca.shared.global [%0],[%1],16;\n" :: "r"(dst), "l"(src));
}
__device__ __forceinline__ void cpcommit() {
    asm volatile("cp.async.commit_group;\n");
}
template<int N_> __device__ __forceinline__ void cpwait() {
    asm volatile("cp.async.wait_group %0;\n" :: "n"(N_));
}
__device__ __forceinline__ void ldsm4(unsigned* r, unsigned a)
{
    asm volatile("ldmatrix.sync.aligned.m8n8.x4.shared.b16 {%0,%1,%2,%3},[%4];\n"
                 : "=r"(r[0]), "=r"(r[1]), "=r"(r[2]), "=r"(r[3]) : "r"(a));
}
__device__ __forceinline__ void ldsm4t(unsigned* r, unsigned a)
{
    asm volatile("ldmatrix.sync.aligned.m8n8.x4.trans.shared.b16 {%0,%1,%2,%3},[%4];\n"
                 : "=r"(r[0]), "=r"(r[1]), "=r"(r[2]), "=r"(r[3]) : "r"(a));
}
__device__ __forceinline__ void mma16816(float* c, const unsigned* a, const unsigned* b)
{
    asm volatile("mma.sync.aligned.m16n8k16.row.col.f32.bf16.bf16.f32 "
                 "{%0,%1,%2,%3},{%4,%5,%6,%7},{%8,%9},{%0,%1,%2,%3};\n"
                 : "+f"(c[0]), "+f"(c[1]), "+f"(c[2]), "+f"(c[3])
                 : "r"(a[0]), "r"(a[1]), "r"(a[2]), "r"(a[3]),
                   "r"(b[0]), "r"(b[1]));
}
__device__ __forceinline__ float gelu_tanh(float t) {
    return 0.5f*t*(1.f + tanhf(0.7978845608028654f*(t + 0.044715f*t*t*t)));
}

// ---------------- weight split (plain, [K][N] stays) -------------------------
__global__ void k_split(const float* __restrict__ src, bf16* __restrict__ h,
                        bf16* __restrict__ l, int n4)
{
    int i = blockIdx.x*256 + threadIdx.x;
    if (i >= n4) return;
    float4 v = ((const float4*)src)[i];
    bf16 hh[4], ll[4];
    split1(v.x, hh[0], ll[0]); split1(v.y, hh[1], ll[1]);
    split1(v.z, hh[2], ll[2]); split1(v.w, hh[3], ll[3]);
    ((uint2*)h)[i] = *(uint2*)hh;
    ((uint2*)l)[i] = *(uint2*)ll;
}

// ---------------- adaLN ------------------------------------------------------
__global__ void k_ada(const float* __restrict__ c,
                      const float* __restrict__ w,
                      const float* __restrict__ bias)
{
    __shared__ float sc[HID];
    int b = blockIdx.y;
    for (int i = threadIdx.x; i < HID; i += blockDim.x) {
        float v = c[b*HID + i];
        sc[i] = v / (1.f + __expf(-v));
    }
    __syncthreads();
    int n = blockIdx.x*128 + threadIdx.x;
    float acc = bias[n];
    #pragma unroll 4
    for (int k = 0; k < HID; k++) acc += sc[k] * w[(size_t)k*(6*HID) + n];
    g_mod[b*6*HID + n] = acc;
}

// ---------------- fused LN + modulate, writes split bf16 ---------------------
__global__ void k_lnmod(const float* __restrict__ x,
                        bf16* __restrict__ oh, bf16* __restrict__ ol,
                        int shofs, int scofs)
{
    int row = blockIdx.x;
    int b   = row / SEQ;
    int t   = threadIdx.x;
    float4 v = ((const float4*)(x + (size_t)row*HID))[t];
    float s  = v.x + v.y + v.z + v.w;
    float ss = v.x*v.x + v.y*v.y + v.z*v.z + v.w*v.w;
    #pragma unroll
    for (int off = 16; off >= 1; off >>= 1) {
        s  += __shfl_xor_sync(0xffffffffu, s , off);
        ss += __shfl_xor_sync(0xffffffffu, ss, off);
    }
    __shared__ float rs[9], rss[9];
    __shared__ float smu, srs;
    if ((t & 31) == 0) { rs[t>>5] = s; rss[t>>5] = ss; }
    __syncthreads();
    if (t == 0) {
        float S = 0.f, SS = 0.f;
        #pragma unroll
        for (int i = 0; i < 9; i++) { S += rs[i]; SS += rss[i]; }
        float mu  = S * (1.f/(float)HID);
        float var = SS * (1.f/(float)HID) - mu*mu;
        smu = mu; srs = rsqrtf(var + EPS);
    }
    __syncthreads();
    float mu = smu, r = srs;
    float4 sh = ((const float4*)(g_mod + b*6*HID + shofs))[t];
    float4 sc = ((const float4*)(g_mod + b*6*HID + scofs))[t];
    float o0 = (1.f+sc.x)*((v.x-mu)*r) + sh.x;
    float o1 = (1.f+sc.y)*((v.y-mu)*r) + sh.y;
    float o2 = (1.f+sc.z)*((v.z-mu)*r) + sh.z;
    float o3 = (1.f+sc.w)*((v.w-mu)*r) + sh.w;
    bf16 hh[4], ll[4];
    split1(o0, hh[0], ll[0]); split1(o1, hh[1], ll[1]);
    split1(o2, hh[2], ll[2]); split1(o3, hh[3], ll[3]);
    ((uint2*)(oh + (size_t)row*HID))[t] = *(uint2*)hh;
    ((uint2*)(ol + (size_t)row*HID))[t] = *(uint2*)ll;
}

// ---------------- mma.sync GEMM (validated Round-3 kernel) -------------------
#define BK 32
#define APAD 40
#define BPAD 136
#define SM_A (128*APAD)
#define SM_B (BK*BPAD)
__global__ __launch_bounds__(256)
void k_gemm_tc(const bf16* __restrict__ Ah, const bf16* __restrict__ Al,
               const bf16* __restrict__ Bh, const bf16* __restrict__ Bl,
               const float* __restrict__ bias,
               float* C, bf16* Ch, bf16* Cl,
               int M, int N, int K, int mode, const float* xres, int gofs)
{
    bf16* smem = (bf16*)dynsmem;
    bf16* sAH = smem;
    bf16* sAL = sAH + 2*SM_A;
    bf16* sBH = sAL + 2*SM_A;
    bf16* sBL = sBH + 2*SM_B;

    const int t    = threadIdx.x;
    const int lane = t & 31;
    const int wid  = t >> 5;
    const int m0   = blockIdx.y * 128;
    const int n0   = blockIdx.x * 128;
    const int wm   = (wid >> 2) * 64;
    const int wn   = (wid & 3) * 32;

    const int arow = t >> 2;
    const int acol = (t & 3) * 8;
    const int brow = t >> 4;
    const int bcol = (t & 15) * 8;

    const int lrow = lane & 15;
    const int lcol = (lane >> 4) * 8;

    float acc[4][4][4];
    #pragma unroll
    for (int i = 0; i < 4; i++)
        #pragma unroll
        for (int j = 0; j < 4; j++)
            #pragma unroll
            for (int q = 0; q < 4; q++) acc[i][j][q] = 0.f;

    const int nIter = K / BK;

    auto issue = [&](int it, int s) {
        int k0 = it * BK;
        bf16* aH = sAH + s*SM_A;  bf16* aL = sAL + s*SM_A;
        bf16* bH = sBH + s*SM_B;  bf16* bL = sBL + s*SM_B;
        #pragma unroll
        for (int p = 0; p < 2; p++) {
            int r = arow + 64*p;
            size_t go = (size_t)(m0 + r)*K + k0 + acol;
            cp16(su32(aH + r*APAD + acol), Ah + go);
            cp16(su32(aL + r*APAD + acol), Al + go);
        }
        #pragma unroll
        for (int p = 0; p < 2; p++) {
            int r = brow + 16*p;
            size_t go = (size_t)(k0 + r)*N + n0 + bcol;
            cp16(su32(bH + r*BPAD + bcol), Bh + go);
            cp16(su32(bL + r*BPAD + bcol), Bl + go);
        }
        cpcommit();
    };

    issue(0, 0);

    for (int it = 0; it < nIter; it++) {
        cpwait<0>();
        __syncthreads();
        if (it + 1 < nIter) issue(it + 1, (it + 1) & 1);

        int s = it & 1;
        bf16* aHs = sAH + s*SM_A;  bf16* aLs = sAL + s*SM_A;
        bf16* bHs = sBH + s*SM_B;  bf16* bLs = sBL + s*SM_B;

        #pragma unroll
        for (int ks = 0; ks < BK; ks += 16) {
            unsigned aH[4][4], aL[4][4], bH[8], bL[8];
            #pragma unroll
            for (int mt = 0; mt < 4; mt++) {
                ldsm4(aH[mt], su32(aHs + (wm + mt*16 + lrow)*APAD + ks + lcol));
                ldsm4(aL[mt], su32(aLs + (wm + mt*16 + lrow)*APAD + ks + lcol));
            }
            #pragma unroll
            for (int bt = 0; bt < 2; bt++) {
                ldsm4t(&bH[bt*4], su32(bHs + (ks + lrow)*BPAD + wn + bt*16 + lcol));
                ldsm4t(&bL[bt*4], su32(bLs + (ks + lrow)*BPAD + wn + bt*16 + lcol));
            }
            #pragma unroll
            for (int mt = 0; mt < 4; mt++)
                #pragma unroll
                for (int nt = 0; nt < 4; nt++) {
                    mma16816(acc[mt][nt], aH[mt], &bH[nt*2]);
                    mma16816(acc[mt][nt], aL[mt], &bH[nt*2]);
                    mma16816(acc[mt][nt], aH[mt], &bL[nt*2]);
                }
        }
        __syncthreads();
    }

    const int gr = lane >> 2;
    const int gc = (lane & 3) * 2;
    #pragma unroll
    for (int mt = 0; mt < 4; mt++) {
        #pragma unroll
        for (int half = 0; half < 2; half++) {
            int row = m0 + wm + mt*16 + gr + half*8;
            int bq  = row / SEQ;
            #pragma unroll
            for (int nt = 0; nt < 4; nt++) {
                int col = n0 + wn + nt*8 + gc;
                float2 bb = *(const float2*)(bias + col);
                float v0 = acc[mt][nt][half*2+0] + bb.x;
                float v1 = acc[mt][nt][half*2+1] + bb.y;
                if (mode == 1) {
                    float2 g  = *(const float2*)(g_mod + bq*6*HID + gofs + col);
                    float2 xr = *(const float2*)(xres + (size_t)row*N + col);
                    v0 = xr.x + g.x*v0;
                    v1 = xr.y + g.y*v1;
                    float2 o; o.x = v0; o.y = v1;
                    *(float2*)(C + (size_t)row*N + col) = o;
                } else if (mode == 2) {
                    v0 = gelu_tanh(v0);
                    v1 = gelu_tanh(v1);
                    *(unsigned*)(Ch + (size_t)row*N + col) = packh2(v0, v1);
                    *(unsigned*)(Cl + (size_t)row*N + col) = packl2(v0, v1);
                } else {
                    float2 o; o.x = v0; o.y = v1;
                    *(float2*)(C + (size_t)row*N + col) = o;
                }
            }
        }
    }
}

// ---------------- RoPE (fp32, in place) --------------------------------------
__global__ void k_rope(const float* __restrict__ cosb, const float* __restrict__ sinb)
{
    int idx = blockIdx.x*256 + threadIdx.x;
    int d = idx % 36;
    int h = (idx / 36) % NH;
    int p = (idx / (36*NH)) % 1024;
    int b = idx / (36*NH*1024);
    int row = b*SEQ + TXT + p;
    size_t base = (size_t)row*(3*HID) + h*HD + d;
    float cv = cosb[p*36 + d], sv = sinb[p*36 + d];
    float q1 = g_qkv[base],        q2 = g_qkv[base+36];
    g_qkv[base]      = q1*cv - q2*sv;
    g_qkv[base+36]   = q1*sv + q2*cv;
    float k1 = g_qkv[base+HID],    k2 = g_qkv[base+HID+36];
    g_qkv[base+HID]    = k1*cv - k2*sv;
    g_qkv[base+HID+36] = k1*sv + k2*cv;
}

// ---------------- qkv split (q scaled by 1/sqrt(HD)) -------------------------
__global__ void k_splitqkv()
{
    const float scale = 0.11785113019775793f;
    size_t i = (size_t)blockIdx.x*256 + threadIdx.x;   // per float4
    float4 v = ((const float4*)g_qkv)[i];
    int col = (int)((i*4) % (3*HID));
    if (col < HID) { v.x*=scale; v.y*=scale; v.z*=scale; v.w*=scale; }
    bf16 hh[4], ll[4];
    split1(v.x, hh[0], ll[0]); split1(v.y, hh[1], ll[1]);
    split1(v.z, hh[2], ll[2]); split1(v.w, hh[3], ll[3]);
    ((uint2*)g_qkvh)[i] = *(uint2*)hh;
    ((uint2*)g_qkvl)[i] = *(uint2*)ll;
}

// ---------------- tensor-core flash attention --------------------------------
// Q tile 128, KV tile 64, 8 warps (16 rows each, full kv width per warp).
// bf16x3 split on both QK^T and PV. head dim padded 72->80 in smem.
#define ATSTR   88                       /* smem row stride (elems) */
#define TILE_Q  (128*ATSTR*2)            /* bytes per Q operand      */
#define TILE_KV (64*ATSTR*2)             /* bytes per K/V operand    */
#define ATT_SMEM (2*TILE_Q + 2*4*TILE_KV)
__global__ __launch_bounds__(256)
void k_attn_tc(const bf16* __restrict__ qh, const bf16* __restrict__ ql,
               bf16* __restrict__ oh, bf16* __restrict__ ol)
{
    char* smem = dynsmem;
    const unsigned sb    = su32(smem);
    const unsigned sQh   = sb;
    const unsigned sQl   = sb + TILE_Q;
    const unsigned sKV0  = sb + 2*TILE_Q;

    const int t    = threadIdx.x;
    const int lane = t & 31;
    const int wid  = t >> 5;
    const int q0   = blockIdx.x * 128;
    const int h    = blockIdx.y;
    const int b    = blockIdx.z;
    const int wm   = wid * 16;
    const int lrow = lane & 15;
    const int lcol = (lane >> 4) * 8;

    // zero all smem (pads must be 0 for the QK k-dim)
    #pragma unroll
    for (int i = 0; i < ATT_SMEM/16/256; i++) {
        uint4 z = {0,0,0,0};
        *(uint4*)(smem + (i*256 + t)*16) = z;
    }
    __syncthreads();

    // stage Q (cp.async): 128 rows x 9 x {h,l} = 2304 cp16
    {
        #pragma unroll
        for (int rep = 0; rep < 9; rep++) {
            int id  = rep*256 + t;
            int op  = id / 1152;
            int rid = id % 1152;
            int row = rid / 9, c8 = rid % 9;
            const bf16* src = (op ? ql : qh)
                + (size_t)(b*SEQ + q0 + row)*(3*HID) + h*HD + c8*8;
            cp16((op ? sQl : sQh) + (row*ATSTR + c8*8)*2, src);
        }
        cpcommit();
    }

    auto stage_kv = [&](int kt, int s) {
        unsigned base = sKV0 + s*4*TILE_KV;
        #pragma unroll
        for (int rep = 0; rep < 9; rep++) {
            int id  = rep*256 + t;          // 0..2303
            int op  = id / 576;             // kh,kl,vh,vl
            int rid = id % 576;
            int row = rid / 9, c8 = rid % 9;
            const bf16* srcb = (op & 1) ? ql : qh;
            int seg = (op >> 1) ? 2*HID : HID;
            const bf16* src = srcb + (size_t)(b*SEQ + kt*64 + row)*(3*HID)
                            + seg + h*HD + c8*8;
            cp16(base + op*TILE_KV + (row*ATSTR + c8*8)*2, src);
        }
        cpcommit();
    };

    stage_kv(0, 0);

    float m0r = -3.0e38f, m1r = -3.0e38f, l0r = 0.f, l1r = 0.f;
    float o[10][4];
    #pragma unroll
    for (int i = 0; i < 10; i++)
        #pragma unroll
        for (int j = 0; j < 4; j++) o[i][j] = 0.f;

    const int NKV = SEQ/64;
    for (int kt = 0; kt < NKV; kt++) {
        cpwait<0>();
        __syncthreads();
        if (kt + 1 < NKV) stage_kv(kt + 1, (kt + 1) & 1);

        unsigned kvb = sKV0 + (kt & 1)*4*TILE_KV;
        unsigned sKh = kvb, sKl = kvb + TILE_KV;
        unsigned sVh = kvb + 2*TILE_KV, sVl = kvb + 3*TILE_KV;

        // ---- S = (scaled Q) K^T, bf16x3 ----
        float s[8][4];
        #pragma unroll
        for (int i = 0; i < 8; i++)
            #pragma unroll
            for (int j = 0; j < 4; j++) s[i][j] = 0.f;

        #pragma unroll
        for (int kc = 0; kc < 5; kc++) {
            unsigned aH[4], aL[4];
            ldsm4(aH, sQh + ((wm + lrow)*ATSTR + kc*16 + lcol)*2);
            ldsm4(aL, sQl + ((wm + lrow)*ATSTR + kc*16 + lcol)*2);
            #pragma unroll
            for (int jt = 0; jt < 4; jt++) {
                unsigned kH[4], kL[4];
                ldsm4(kH, sKh + ((jt*16 + lrow)*ATSTR + kc*16 + lcol)*2);
                ldsm4(kL, sKl + ((jt*16 + lrow)*ATSTR + kc*16 + lcol)*2);
                // non-trans K[j][d]: frag pairs {r0,r2} (j lo8), {r1,r3} (j hi8)
                unsigned bh0[2] = {kH[0], kH[2]}, bh1[2] = {kH[1], kH[3]};
                unsigned bl0[2] = {kL[0], kL[2]}, bl1[2] = {kL[1], kL[3]};
                mma16816(s[jt*2],   aH, bh0);
                mma16816(s[jt*2],   aL, bh0);
                mma16816(s[jt*2],   aH, bl0);
                mma16816(s[jt*2+1], aH, bh1);
                mma16816(s[jt*2+1], aL, bh1);
                mma16816(s[jt*2+1], aH, bl1);
            }
        }

        // ---- online softmax (rows r = lane>>2 and r+8, per warp) ----
        float tm0 = -3.0e38f, tm1 = -3.0e38f;
        #pragma unroll
        for (int f = 0; f < 8; f++) {
            tm0 = fmaxf(tm0, fmaxf(s[f][0], s[f][1]));
            tm1 = fmaxf(tm1, fmaxf(s[f][2], s[f][3]));
        }
        #pragma unroll
        for (int off = 1; off <= 2; off <<= 1) {
            tm0 = fmaxf(tm0, __shfl_xor_sync(0xffffffffu, tm0, off));
            tm1 = fmaxf(tm1, __shfl_xor_sync(0xffffffffu, tm1, off));
        }
        float nm0 = fmaxf(m0r, tm0), nm1 = fmaxf(m1r, tm1);
        float cf0 = __expf(m0r - nm0), cf1 = __expf(m1r - nm1);
        m0r = nm0; m1r = nm1;

        float rs0 = 0.f, rs1 = 0.f;
        #pragma unroll
        for (int f = 0; f < 8; f++) {
            s[f][0] = __expf(s[f][0] - nm0);
            s[f][1] = __expf(s[f][1] - nm0);
            s[f][2] = __expf(s[f][2] - nm1);
            s[f][3] = __expf(s[f][3] - nm1);
            rs0 += s[f][0] + s[f][1];
            rs1 += s[f][2] + s[f][3];
        }
        #pragma unroll
        for (int off = 1; off <= 2; off <<= 1) {
            rs0 += __shfl_xor_sync(0xffffffffu, rs0, off);
            rs1 += __shfl_xor_sync(0xffffffffu, rs1, off);
        }
        l0r = l0r*cf0 + rs0;
        l1r = l1r*cf1 + rs1;

        #pragma unroll
        for (int i = 0; i < 10; i++) {
            o[i][0] *= cf0; o[i][1] *= cf0;
            o[i][2] *= cf1; o[i][3] *= cf1;
        }

        // ---- O += P V, bf16x3 (P from S frags, in registers) ----
        #pragma unroll
        for (int kc = 0; kc < 4; kc++) {
            float* f0 = s[kc*2];
            float* f1 = s[kc*2+1];
            unsigned aP [4] = { packh2(f0[0], f0[1]), packh2(f0[2], f0[3]),
                                packh2(f1[0], f1[1]), packh2(f1[2], f1[3]) };
            unsigned aPl[4] = { packl2(f0[0], f0[1]), packl2(f0[2], f0[3]),
                                packl2(f1[0], f1[1]), packl2(f1[2], f1[3]) };
            #pragma unroll
            for (int dt = 0; dt < 5; dt++) {
                unsigned vH[4], vL[4];
                ldsm4t(vH, sVh + ((kc*16 + lrow)*ATSTR + dt*16 + lcol)*2);
                ldsm4t(vL, sVl + ((kc*16 + lrow)*ATSTR + dt*16 + lcol)*2);
                mma16816(o[dt*2],   aP,  &vH[0]);
                mma16816(o[dt*2],   aPl, &vH[0]);
                mma16816(o[dt*2],   aP,  &vL[0]);
                mma16816(o[dt*2+1], aP,  &vH[2]);
                mma16816(o[dt*2+1], aPl, &vH[2]);
                mma16816(o[dt*2+1], aP,  &vL[2]);
            }
        }
        __syncthreads();
    }

    // ---- epilogue: O /= l, split-store (cols < 72 only) ----
    float i0 = 1.f / l0r, i1 = 1.f / l1r;
    int r0 = b*SEQ + q0 + wm + (lane >> 2);
    int r1 = r0 + 8;
    int gc = (lane & 3) * 2;
    #pragma unroll
    for (int nt = 0; nt < 9; nt++) {
        int col = nt*8 + gc;
        float v0 = o[nt][0]*i0, v1 = o[nt][1]*i0;
        float v2 = o[nt][2]*i1, v3 = o[nt][3]*i1;
        size_t off0 = (size_t)r0*HID + h*HD + col;
        size_t off1 = (size_t)r1*HID + h*HD + col;
        *(unsigned*)(oh + off0) = packh2(v0, v1);
        *(unsigned*)(ol + off0) = packl2(v0, v1);
        *(unsigned*)(oh + off1) = packh2(v2, v3);
        *(unsigned*)(ol + off1) = packl2(v2, v3);
    }
}

// ---------------- launcher ---------------------------------------------------
extern "C" void kernel_launch(void* const* d_in, const int* in_sizes, int n_in,
                              void* d_out, int out_size)
{
    const float* x      = (const float*)d_in[0];
    const float* c      = (const float*)d_in[1];
    const float* cosb   = (const float*)d_in[2];
    const float* sinb   = (const float*)d_in[3];
    const float* w_qkv  = (const float*)d_in[4];
    const float* b_qkv  = (const float*)d_in[5];
    const float* w_proj = (const float*)d_in[6];
    const float* b_proj = (const float*)d_in[7];
    const float* w_mlp1 = (const float*)d_in[8];
    const float* b_mlp1 = (const float*)d_in[9];
    const float* w_mlp2 = (const float*)d_in[10];
    const float* b_mlp2 = (const float*)d_in[11];
    const float* w_ada  = (const float*)d_in[12];
    const float* b_ada  = (const float*)d_in[13];
    float* out = (float*)d_out;

    float *qkv;
    bf16 *qkvh, *qkvl, *resh, *resl, *attnh, *attnl, *hh, *hl;
    bf16 *wqkvh, *wqkvl, *wprojh, *wprojl, *wm1h, *wm1l, *wm2h, *wm2l;
    cudaGetSymbolAddress((void**)&qkv,   g_qkv);
    cudaGetSymbolAddress((void**)&qkvh,  g_qkvh);
    cudaGetSymbolAddress((void**)&qkvl,  g_qkvl);
    cudaGetSymbolAddress((void**)&resh,  g_resh);
    cudaGetSymbolAddress((void**)&resl,  g_resl);
    cudaGetSymbolAddress((void**)&attnh, g_attnh);
    cudaGetSymbolAddress((void**)&attnl, g_attnl);
    cudaGetSymbolAddress((void**)&hh,    g_hh);
    cudaGetSymbolAddress((void**)&hl,    g_hl);
    cudaGetSymbolAddress((void**)&wqkvh, g_wqkvh);
    cudaGetSymbolAddress((void**)&wqkvl, g_wqkvl);
    cudaGetSymbolAddress((void**)&wprojh,g_wprojh);
    cudaGetSymbolAddress((void**)&wprojl,g_wprojl);
    cudaGetSymbolAddress((void**)&wm1h,  g_wm1h);
    cudaGetSymbolAddress((void**)&wm1l,  g_wm1l);
    cudaGetSymbolAddress((void**)&wm2h,  g_wm2h);
    cudaGetSymbolAddress((void**)&wm2l,  g_wm2l);

    // 0. split weights ([K][N] layout, GEMM B operand)
    k_split<<<(HID*3*HID/4 + 255)/256, 256>>>(w_qkv,  wqkvh,  wqkvl,  HID*3*HID/4);
    k_split<<<(HID*HID/4   + 255)/256, 256>>>(w_proj, wprojh, wprojl, HID*HID/4);
    k_split<<<(HID*4*HID/4 + 255)/256, 256>>>(w_mlp1, wm1h,   wm1l,   HID*4*HID/4);
    k_split<<<(4*HID*HID/4 + 255)/256, 256>>>(w_mlp2, wm2h,   wm2l,   4*HID*HID/4);

    // 1-2. adaLN + LN/modulate
    k_ada<<<dim3(6*HID/128, BATCH), 128>>>(c, w_ada, b_ada);
    k_lnmod<<<TOK, 288>>>(x, resh, resl, 0, HID);

    int gsmem = (2*SM_A + 2*SM_B) * 2 * (int)sizeof(bf16);
    cudaFuncSetAttribute(k_gemm_tc, cudaFuncAttributeMaxDynamicSharedMemorySize, gsmem);

    // 3. qkv GEMM
    k_gemm_tc<<<dim3(3*HID/128, TOK/128), 256, gsmem>>>(
        resh, resl, wqkvh, wqkvl, b_qkv, qkv, nullptr, nullptr,
        TOK, 3*HID, HID, 0, nullptr, 0);
    // 4. RoPE + split qkv (q scaled)
    k_rope<<<(BATCH*1024*NH*36)/256, 256>>>(cosb, sinb);
    k_splitqkv<<<TOK*3*HID/4/256, 256>>>();
    // 5. tensor-core attention
    cudaFuncSetAttribute(k_attn_tc, cudaFuncAttributeMaxDynamicSharedMemorySize,
                         ATT_SMEM);
    k_attn_tc<<<dim3(SEQ/128, NH, BATCH), 256, ATT_SMEM>>>(qkvh, qkvl,
                                                           attnh, attnl);
    // 6. proj GEMM + gated residual -> out = x1
    k_gemm_tc<<<dim3(HID/128, TOK/128), 256, gsmem>>>(
        attnh, attnl, wprojh, wprojl, b_proj, out, nullptr, nullptr,
        TOK, HID, HID, 1, x, 2*HID);
    // 7. LN + modulate (mlp)
    k_lnmod<<<TOK, 288>>>(out, resh, resl, 3*HID, 4*HID);
    // 8. mlp1 GEMM + gelu
    k_gemm_tc<<<dim3(4*HID/128, TOK/128), 256, gsmem>>>(
        resh, resl, wm1h, wm1l, b_mlp1, nullptr, hh, hl,
        TOK, 4*HID, HID, 2, nullptr, 0);
    // 9. mlp2 GEMM + gated residual (in-place on out)
    k_gemm_tc<<<dim3(HID/128, TOK/128), 256, gsmem>>>(
        hh, hl, wm2h, wm2l, b_mlp2, out, nullptr, nullptr,
        TOK, HID, 4*HID, 1, out, 5*HID);
}